// round 15
// baseline (speedup 1.0000x reference)
#include <cuda_runtime.h>
#include <cuda_fp16.h>

#define N_NODES 100000
#define E_EDGES 1600000
#define NB_SCAN 98   // ceil(100000/1024)
#define COL_MASK 0x1FFFF   // node ids < 2^17; rank packed in bits [17:31]

// ---------------- scratch (device globals; no allocations allowed) ----------
__device__ int    g_is64;
__device__ int    g_arrive;               // grid-arrive counter for k_scan
__device__ int2   g_rc[E_EDGES];          // x = row, y = col | (rank<<17)
__device__ int    g_degi[N_NODES];        // in-degree (edges only)
__device__ int    g_part[NB_SCAN];        // per-block total sums
__device__ int    g_start[N_NODES];       // CSR offsets (exclusive)
__device__ int    g_csr[E_EDGES];         // source node per in-edge, grouped by target
__device__ float  g_dinv[N_NODES];
__device__ float2 g_dx[N_NODES];          // dinv[v] * x[v]
__device__ float2 g_p[N_NODES];           // pre1 = dinv*(agg + dx)
__device__ __half g_s2[N_NODES * 32];     // dinv[v] * (h1[v] @ W2)   (fp16)
__device__ __half g_pre2[N_NODES * 32];   // dinv*(agg2 + s2[v])      (fp16)
__device__ __half g_a[N_NODES * 16];      // h2[v] @ Wm1[0:32]        (fp16)
__device__ __half g_c[N_NODES * 16];      // h2[v] @ Wm1[32:64]       (fp16)

// ---------------- setup kernels ----------------------------------------------

__global__ void k_zero_detect(const int* ei32) {
    if (blockIdx.x == 0) {
        __shared__ int s_any;
        if (threadIdx.x == 0) { s_any = 0; g_arrive = 0; }
        __syncthreads();
        int v = 0;
        for (int i = threadIdx.x; i < 1024; i += blockDim.x)
            v |= ei32[2 * i + 1];
        if (v) atomicOr(&s_any, 1);
        __syncthreads();
        if (threadIdx.x == 0) g_is64 = (s_any == 0) ? 1 : 0;
    } else {
        int i = (blockIdx.x - 1) * 256 + threadIdx.x;
        if (i < N_NODES) g_degi[i] = 0;
    }
}

// Convert indices (2 edges/thread, 16B loads); count in-degree on col and
// pack each edge's rank into the col word so CSR fill needs no atomics.
__global__ void k_convert(const void* ei) {
    int e2 = blockIdx.x * blockDim.x + threadIdx.x;
    if (e2 >= E_EDGES / 2) return;
    int r0, r1, c0, c1;
    if (g_is64) {
        const longlong2* p = (const longlong2*)ei;
        longlong2 rr = p[e2];
        longlong2 cc = p[E_EDGES / 2 + e2];
        r0 = (int)rr.x; r1 = (int)rr.y;
        c0 = (int)cc.x; c1 = (int)cc.y;
    } else {
        const int2* p = (const int2*)ei;
        int2 rr = p[e2];
        int2 cc = p[E_EDGES / 2 + e2];
        r0 = rr.x; r1 = rr.y;
        c0 = cc.x; c1 = cc.y;
    }
    int rank0 = atomicAdd(&g_degi[c0], 1);
    int rank1 = atomicAdd(&g_degi[c1], 1);
    int e = 2 * e2;
    g_rc[e]     = make_int2(r0, c0 | (rank0 << 17));
    g_rc[e + 1] = make_int2(r1, c1 | (rank1 << 17));
}

// Single-pass scan + finalize: 98 resident blocks, local shuffle scan,
// grid-arrive, cross-block prefix, then start/dinv/dx per node.
__global__ void k_scan(const float* __restrict__ x) {
    __shared__ int ws[32];
    __shared__ int s_excl;
    int lane = threadIdx.x & 31;
    int warp = threadIdx.x >> 5;
    int i = blockIdx.x * 1024 + threadIdx.x;
    int deg = (i < N_NODES) ? g_degi[i] : 0;
    int s = deg;
#pragma unroll
    for (int o = 1; o < 32; o <<= 1) {
        int t = __shfl_up_sync(0xffffffffu, s, o);
        if (lane >= o) s += t;
    }
    if (lane == 31) ws[warp] = s;
    __syncthreads();
    if (warp == 0) {
        int w = ws[lane];
#pragma unroll
        for (int o = 1; o < 32; o <<= 1) {
            int t = __shfl_up_sync(0xffffffffu, w, o);
            if (lane >= o) w += t;
        }
        ws[lane] = w;
    }
    __syncthreads();
    int incl = s + (warp ? ws[warp - 1] : 0);

    if (threadIdx.x == 1023) {
        g_part[blockIdx.x] = incl;      // block total
        __threadfence();
        atomicAdd(&g_arrive, 1);
    }
    if (warp == 0) {
        if (lane == 0) {
            while (atomicAdd(&g_arrive, 0) < NB_SCAN) { }
        }
        __syncwarp();
        __threadfence();
        int acc = 0;
        for (int b = lane; b < blockIdx.x; b += 32)
            acc += g_part[b];
#pragma unroll
        for (int o = 16; o; o >>= 1)
            acc += __shfl_xor_sync(0xffffffffu, acc, o);
        if (lane == 0) s_excl = acc;
    }
    __syncthreads();

    if (i < N_NODES) {
        g_start[i] = incl - deg + s_excl;
        float dinv = rsqrtf((float)deg + 1.0f);
        g_dinv[i] = dinv;
        float2 xv = ((const float2*)x)[i];
        g_dx[i] = make_float2(dinv * xv.x, dinv * xv.y);
    }
}

// Atomic-free CSR fill: 2 edges/thread, packed ranks, streaming csr writes.
__global__ void k_fill() {
    int e2 = blockIdx.x * blockDim.x + threadIdx.x;
    if (e2 >= E_EDGES / 2) return;
    int4 rr = ((const int4*)g_rc)[e2];   // (r0, y0, r1, y1)
    int c0 = rr.y & COL_MASK, k0 = rr.y >> 17;
    int c1 = rr.w & COL_MASK, k1 = rr.w >> 17;
    int s0 = __ldg(&g_start[c0]);
    int s1 = __ldg(&g_start[c1]);
    __stcs(&g_csr[s0 + k0], rr.x);
    __stcs(&g_csr[s1 + k1], rr.z);
}

// ---------------- layer 1: gather then tiled GEMM -----------------------------

// Thread-per-node: p[v] = dinv * (sum_{r in in(v)} dx[r] + dx[v])
__global__ void k_gather1() {
    int v = blockIdx.x * blockDim.x + threadIdx.x;
    if (v >= N_NODES) return;
    int start = g_start[v];
    int deg   = g_degi[v];
    float a0 = 0.0f, a1 = 0.0f;
    int i = 0;
    for (; i + 4 <= deg; i += 4) {
        int r0 = g_csr[start + i];
        int r1 = g_csr[start + i + 1];
        int r2 = g_csr[start + i + 2];
        int r3 = g_csr[start + i + 3];
        float2 d0 = g_dx[r0], d1 = g_dx[r1], d2 = g_dx[r2], d3 = g_dx[r3];
        a0 += d0.x + d1.x + d2.x + d3.x;
        a1 += d0.y + d1.y + d2.y + d3.y;
    }
    for (; i < deg; i++) {
        float2 d = g_dx[g_csr[start + i]];
        a0 += d.x;
        a1 += d.y;
    }
    float dinv = g_dinv[v];
    float2 dxv = g_dx[v];
    g_p[v] = make_float2(dinv * (a0 + dxv.x), dinv * (a1 + dxv.y));
}

// Tiled GEMM: for 128-node tile, H[64][128] = relu(p @ W1 + b1) in shared,
// then s2 = dinv * (H^T @ W2) with 4n x 4k register tiles.
__global__ void k_mlp1(const float* __restrict__ W1,
                       const float* __restrict__ b1,
                       const float* __restrict__ W2) {
    __shared__ float sW1a[64], sW1b[64], sb1[64];
    __shared__ float sW2s[64][32];
    __shared__ float sH[64][128];
    __shared__ float sp0[128], sp1[128], sdinv[128];

    int tid = threadIdx.x;
    int base = blockIdx.x * 128;

    for (int i = tid; i < 64; i += 256) {
        sW1a[i] = W1[i];
        sW1b[i] = W1[64 + i];
        sb1[i]  = b1[i];
    }
    for (int i = tid; i < 2048; i += 256)
        sW2s[i >> 5][i & 31] = W2[i];
    if (tid < 128) {
        int gn = base + tid;
        if (gn < N_NODES) {
            float2 p = g_p[gn];
            sp0[tid] = p.x;
            sp1[tid] = p.y;
            sdinv[tid] = g_dinv[gn];
        } else {
            sp0[tid] = 0.0f; sp1[tid] = 0.0f; sdinv[tid] = 0.0f;
        }
    }
    __syncthreads();

    for (int idx = tid; idx < 8192; idx += 256) {
        int j = idx >> 7, n = idx & 127;
        float h = fmaf(sp0[n], sW1a[j], fmaf(sp1[n], sW1b[j], sb1[j]));
        sH[j][n] = fmaxf(h, 0.0f);
    }
    __syncthreads();

    int kt = tid & 7, nt = tid >> 3;
    int n0 = nt * 4, k0 = kt * 4;
    float4 acc0 = make_float4(0,0,0,0), acc1 = acc0, acc2 = acc0, acc3 = acc0;
#pragma unroll
    for (int j = 0; j < 64; j++) {
        float4 h4 = *(const float4*)&sH[j][n0];
        float4 w4 = *(const float4*)&sW2s[j][k0];
        acc0.x = fmaf(h4.x, w4.x, acc0.x); acc0.y = fmaf(h4.x, w4.y, acc0.y);
        acc0.z = fmaf(h4.x, w4.z, acc0.z); acc0.w = fmaf(h4.x, w4.w, acc0.w);
        acc1.x = fmaf(h4.y, w4.x, acc1.x); acc1.y = fmaf(h4.y, w4.y, acc1.y);
        acc1.z = fmaf(h4.y, w4.z, acc1.z); acc1.w = fmaf(h4.y, w4.w, acc1.w);
        acc2.x = fmaf(h4.z, w4.x, acc2.x); acc2.y = fmaf(h4.z, w4.y, acc2.y);
        acc2.z = fmaf(h4.z, w4.z, acc2.z); acc2.w = fmaf(h4.z, w4.w, acc2.w);
        acc3.x = fmaf(h4.w, w4.x, acc3.x); acc3.y = fmaf(h4.w, w4.y, acc3.y);
        acc3.z = fmaf(h4.w, w4.z, acc3.z); acc3.w = fmaf(h4.w, w4.w, acc3.w);
    }
    float4 accs[4] = {acc0, acc1, acc2, acc3};
#pragma unroll
    for (int a = 0; a < 4; a++) {
        int n = n0 + a, gn = base + n;
        if (gn < N_NODES) {
            float d = sdinv[n];
            __half2 h01 = __floats2half2_rn(d * accs[a].x, d * accs[a].y);
            __half2 h23 = __floats2half2_rn(d * accs[a].z, d * accs[a].w);
            uint2 o;
            o.x = *(unsigned*)&h01;
            o.y = *(unsigned*)&h23;
            *(uint2*)&g_s2[gn * 32 + k0] = o;
        }
    }
}

// ---------------- layer 2: gather then tiled GEMM -----------------------------

// Warp-per-node, 16 rows in flight (pairwise fp16 hadd2 tree before cvt).
// Writes pre2 = dinv*(agg + s2[v]) fp16. 512-thread blocks.
__global__ void k_gather2() {
    int warp = threadIdx.x >> 5;
    int lane = threadIdx.x & 31;
    int v = blockIdx.x * 16 + warp;
    if (v >= N_NODES) return;

    int sub = lane >> 2;        // 0..7 row-groups
    int q   = lane & 3;         // dims 8q..8q+7
    int start = g_start[v];
    int deg   = g_degi[v];

    const uint4* s2v = (const uint4*)g_s2;
    float S[8] = {0.f,0.f,0.f,0.f,0.f,0.f,0.f,0.f};
    int i = sub;
    for (; i + 8 < deg; i += 16) {
        int r1 = g_csr[start + i];
        int r2 = g_csr[start + i + 8];
        uint4 u = s2v[r1 * 4 + q];
        uint4 w = s2v[r2 * 4 + q];
        __half2 h0 = __hadd2(*(const __half2*)&u.x, *(const __half2*)&w.x);
        __half2 h1 = __hadd2(*(const __half2*)&u.y, *(const __half2*)&w.y);
        __half2 h2 = __hadd2(*(const __half2*)&u.z, *(const __half2*)&w.z);
        __half2 h3 = __hadd2(*(const __half2*)&u.w, *(const __half2*)&w.w);
        float2 f0 = __half22float2(h0);
        float2 f1 = __half22float2(h1);
        float2 f2 = __half22float2(h2);
        float2 f3 = __half22float2(h3);
        S[0] += f0.x; S[1] += f0.y; S[2] += f1.x; S[3] += f1.y;
        S[4] += f2.x; S[5] += f2.y; S[6] += f3.x; S[7] += f3.y;
    }
    if (i < deg) {
        int r = g_csr[start + i];
        uint4 u = s2v[r * 4 + q];
        float2 f0 = __half22float2(*(const __half2*)&u.x);
        float2 f1 = __half22float2(*(const __half2*)&u.y);
        float2 f2 = __half22float2(*(const __half2*)&u.z);
        float2 f3 = __half22float2(*(const __half2*)&u.w);
        S[0] += f0.x; S[1] += f0.y; S[2] += f1.x; S[3] += f1.y;
        S[4] += f2.x; S[5] += f2.y; S[6] += f3.x; S[7] += f3.y;
    }
#pragma unroll
    for (int o = 4; o <= 16; o <<= 1) {
#pragma unroll
        for (int t = 0; t < 8; t++)
            S[t] += __shfl_xor_sync(0xffffffffu, S[t], o);
    }

    if (sub == 0) {
        float dinv = g_dinv[v];
        uint4 u = s2v[v * 4 + q];
        float2 f0 = __half22float2(*(const __half2*)&u.x);
        float2 f1 = __half22float2(*(const __half2*)&u.y);
        float2 f2 = __half22float2(*(const __half2*)&u.z);
        float2 f3 = __half22float2(*(const __half2*)&u.w);
        __half2 p0 = __floats2half2_rn(dinv * (S[0] + f0.x), dinv * (S[1] + f0.y));
        __half2 p1 = __floats2half2_rn(dinv * (S[2] + f1.x), dinv * (S[3] + f1.y));
        __half2 p2 = __floats2half2_rn(dinv * (S[4] + f2.x), dinv * (S[5] + f2.y));
        __half2 p3 = __floats2half2_rn(dinv * (S[6] + f3.x), dinv * (S[7] + f3.y));
        uint4 o;
        o.x = *(unsigned*)&p0; o.y = *(unsigned*)&p1;
        o.z = *(unsigned*)&p2; o.w = *(unsigned*)&p3;
        ((uint4*)g_pre2)[v * 4 + q] = o;
    }
}

// Tiled GEMM: h2 = relu(pre2 + b2) staged to shared, then
// (a|c)[n][k] = sum_j h2[n][j] * Wq[j][k].
__global__ void k_mlp2(const float* __restrict__ b2,
                       const float* __restrict__ Wm1) {
    __shared__ float sW[32][32];
    __shared__ float sH2[32][132];
    __shared__ float sb2[32];

    int tid = threadIdx.x;
    int base = blockIdx.x * 128;

    if (tid < 32) sb2[tid] = b2[tid];
    for (int i = tid; i < 1024; i += 256) {
        int j = i >> 5, k = i & 31;
        sW[j][k] = Wm1[((k < 16 ? j : 32 + j) << 4) + (k & 15)];
    }
    __syncthreads();

    const __half2* src = (const __half2*)g_pre2;
    for (int idx = tid; idx < 2048; idx += 256) {
        int n = idx >> 4;
        int j2 = idx & 15;
        int gn = base + n;
        float2 f = make_float2(0.0f, 0.0f);
        if (gn < N_NODES)
            f = __half22float2(src[gn * 16 + j2]);
        int j = 2 * j2;
        sH2[j][n]     = fmaxf(f.x + sb2[j],     0.0f);
        sH2[j + 1][n] = fmaxf(f.y + sb2[j + 1], 0.0f);
    }
    __syncthreads();

    int kt = tid & 7, nt = tid >> 3;
    int n0 = nt * 4, k0 = kt * 4;
    float4 acc0 = make_float4(0,0,0,0), acc1 = acc0, acc2 = acc0, acc3 = acc0;
#pragma unroll
    for (int j = 0; j < 32; j++) {
        float4 h4 = *(const float4*)&sH2[j][n0];
        float4 w4 = *(const float4*)&sW[j][k0];
        acc0.x = fmaf(h4.x, w4.x, acc0.x); acc0.y = fmaf(h4.x, w4.y, acc0.y);
        acc0.z = fmaf(h4.x, w4.z, acc0.z); acc0.w = fmaf(h4.x, w4.w, acc0.w);
        acc1.x = fmaf(h4.y, w4.x, acc1.x); acc1.y = fmaf(h4.y, w4.y, acc1.y);
        acc1.z = fmaf(h4.y, w4.z, acc1.z); acc1.w = fmaf(h4.y, w4.w, acc1.w);
        acc2.x = fmaf(h4.z, w4.x, acc2.x); acc2.y = fmaf(h4.z, w4.y, acc2.y);
        acc2.z = fmaf(h4.z, w4.z, acc2.z); acc2.w = fmaf(h4.z, w4.w, acc2.w);
        acc3.x = fmaf(h4.w, w4.x, acc3.x); acc3.y = fmaf(h4.w, w4.y, acc3.y);
        acc3.z = fmaf(h4.w, w4.z, acc3.z); acc3.w = fmaf(h4.w, w4.w, acc3.w);
    }
    float4 accs[4] = {acc0, acc1, acc2, acc3};
#pragma unroll
    for (int a = 0; a < 4; a++) {
        int n = n0 + a, gn = base + n;
        if (gn < N_NODES) {
            __half2 h01 = __floats2half2_rn(accs[a].x, accs[a].y);
            __half2 h23 = __floats2half2_rn(accs[a].z, accs[a].w);
            uint2 o;
            o.x = *(unsigned*)&h01;
            o.y = *(unsigned*)&h23;
            if (k0 < 16) *(uint2*)&g_a[gn * 16 + k0]        = o;
            else         *(uint2*)&g_c[gn * 16 + (k0 - 16)] = o;
        }
    }
}

// ---------------- edge MLP -----------------------------------------------------

// 2 lanes per edge (8 dims each, uint4 gathers); weights staged in shared float4.
__global__ void k_edge(const float* __restrict__ ea,
                       const float* __restrict__ Wm1,
                       const float* __restrict__ bm1,
                       const float* __restrict__ Wm2,
                       const float* __restrict__ bm2,
                       float* __restrict__ out) {
    __shared__ float4 swq[16];   // (W64, W65, bm1, Wm2) per dim
    __shared__ float sbm2;
    if (threadIdx.x < 16)
        swq[threadIdx.x] = make_float4(Wm1[64 * 16 + threadIdx.x],
                                       Wm1[65 * 16 + threadIdx.x],
                                       bm1[threadIdx.x],
                                       Wm2[threadIdx.x]);
    if (threadIdx.x == 0) sbm2 = bm2[0];
    __syncthreads();

    int t = blockIdx.x * blockDim.x + threadIdx.x;
    int e = t >> 1;
    int g = t & 1;              // dims 8g..8g+7
    if (e >= E_EDGES) return;

    int2 rc = g_rc[e];
    int rnode = rc.x;
    int cnode = rc.y & COL_MASK;
    float2 eav = ((const float2*)ea)[e];
    uint4 au = ((const uint4*)g_a)[rnode * 2 + g];
    uint4 cu = ((const uint4*)g_c)[cnode * 2 + g];

    float af[8], cf[8];
    {
        float2 f;
        f = __half22float2(*(const __half2*)&au.x); af[0]=f.x; af[1]=f.y;
        f = __half22float2(*(const __half2*)&au.y); af[2]=f.x; af[3]=f.y;
        f = __half22float2(*(const __half2*)&au.z); af[4]=f.x; af[5]=f.y;
        f = __half22float2(*(const __half2*)&au.w); af[6]=f.x; af[7]=f.y;
        f = __half22float2(*(const __half2*)&cu.x); cf[0]=f.x; cf[1]=f.y;
        f = __half22float2(*(const __half2*)&cu.y); cf[2]=f.x; cf[3]=f.y;
        f = __half22float2(*(const __half2*)&cu.z); cf[4]=f.x; cf[5]=f.y;
        f = __half22float2(*(const __half2*)&cu.w); cf[6]=f.x; cf[7]=f.y;
    }

    float p = 0.0f;
#pragma unroll
    for (int j = 0; j < 8; j++) {
        float4 w = swq[8 * g + j];
        float hm = fmaxf(fmaf(eav.x, w.x, fmaf(eav.y, w.y, af[j] + cf[j] + w.z)), 0.0f);
        p = fmaf(hm, w.w, p);
    }
    p += __shfl_xor_sync(0xffffffffu, p, 1, 2);
    if (g == 0) out[e] = p + sbm2;
}

// ---------------- launch ------------------------------------------------------

extern "C" void kernel_launch(void* const* d_in, const int* in_sizes, int n_in,
                              void* d_out, int out_size) {
    const float* x   = (const float*)d_in[0];
    const void*  ei  = d_in[1];
    const float* ea  = (const float*)d_in[2];
    const float* W1  = (const float*)d_in[3];
    const float* b1  = (const float*)d_in[4];
    const float* W2  = (const float*)d_in[5];
    const float* b2  = (const float*)d_in[6];
    const float* Wm1 = (const float*)d_in[7];
    const float* bm1 = (const float*)d_in[8];
    const float* Wm2 = (const float*)d_in[9];
    const float* bm2 = (const float*)d_in[10];
    float* out = (float*)d_out;

    long long ethreads = (long long)E_EDGES * 2;
    unsigned eblocks = (unsigned)((ethreads + 511) / 512);
    unsigned ntiles = (N_NODES + 127) / 128;

    k_zero_detect<<<(N_NODES + 255) / 256 + 1, 256>>>((const int*)ei);
    k_convert<<<(E_EDGES / 2 + 255) / 256, 256>>>(ei);
    k_scan<<<NB_SCAN, 1024>>>(x);
    k_fill<<<(E_EDGES / 2 + 255) / 256, 256>>>();
    k_gather1<<<(N_NODES + 255) / 256, 256>>>();
    k_mlp1<<<ntiles, 256>>>(W1, b1, W2);
    k_gather2<<<(N_NODES + 15) / 16, 512>>>();
    k_mlp2<<<ntiles, 256>>>(b2, Wm1);
    k_edge<<<eblocks, 512>>>(ea, Wm1, bm1, Wm2, bm2, out);
}

// round 16
// speedup vs baseline: 1.0354x; 1.0354x over previous
#include <cuda_runtime.h>
#include <cuda_fp16.h>

#define N_NODES 100000
#define E_EDGES 1600000
#define NB_SCAN 98   // ceil(100000/1024)
#define COL_MASK 0x1FFFF   // node ids < 2^17; rank packed in bits [17:31]

// ---------------- scratch (device globals; no allocations allowed) ----------
__device__ int    g_is64;
__device__ int    g_arrive;               // grid-arrive counter for k_scan
__device__ int2   g_rc[E_EDGES];          // x = row, y = col | (rank<<17)
__device__ int    g_degi[N_NODES];        // in-degree (edges only)
__device__ int    g_part[NB_SCAN];        // per-block total sums
__device__ int    g_start[N_NODES];       // CSR offsets (exclusive)
__device__ int    g_csr[E_EDGES];         // source node per in-edge, grouped by target
__device__ float  g_dinv[N_NODES];
__device__ float2 g_dx[N_NODES];          // dinv[v] * x[v]
__device__ float2 g_p[N_NODES];           // pre1 = dinv*(agg + dx)
__device__ __half g_s2[N_NODES * 32];     // dinv[v] * (h1[v] @ W2)   (fp16)
__device__ __half g_pre2[N_NODES * 32];   // dinv*(agg2 + s2[v])      (fp16)
__device__ __half g_a[N_NODES * 16];      // h2[v] @ Wm1[0:32]        (fp16)
__device__ __half g_c[N_NODES * 16];      // h2[v] @ Wm1[32:64]       (fp16)

// ---------------- setup kernels ----------------------------------------------

__global__ void k_zero_detect(const int* ei32) {
    if (blockIdx.x == 0) {
        __shared__ int s_any;
        if (threadIdx.x == 0) { s_any = 0; g_arrive = 0; }
        __syncthreads();
        int v = 0;
        for (int i = threadIdx.x; i < 1024; i += blockDim.x)
            v |= ei32[2 * i + 1];
        if (v) atomicOr(&s_any, 1);
        __syncthreads();
        if (threadIdx.x == 0) g_is64 = (s_any == 0) ? 1 : 0;
    } else {
        int i = (blockIdx.x - 1) * 256 + threadIdx.x;
        if (i < N_NODES) g_degi[i] = 0;
    }
}

// Convert indices (2 edges/thread, 16B loads); count in-degree on col and
// pack each edge's rank into the col word so CSR fill needs no atomics.
__global__ void k_convert(const void* ei) {
    cudaGridDependencySynchronize();   // PDL: wait for zero_detect
    int e2 = blockIdx.x * blockDim.x + threadIdx.x;
    if (e2 >= E_EDGES / 2) return;
    int r0, r1, c0, c1;
    if (g_is64) {
        const longlong2* p = (const longlong2*)ei;
        longlong2 rr = p[e2];
        longlong2 cc = p[E_EDGES / 2 + e2];
        r0 = (int)rr.x; r1 = (int)rr.y;
        c0 = (int)cc.x; c1 = (int)cc.y;
    } else {
        const int2* p = (const int2*)ei;
        int2 rr = p[e2];
        int2 cc = p[E_EDGES / 2 + e2];
        r0 = rr.x; r1 = rr.y;
        c0 = cc.x; c1 = cc.y;
    }
    int rank0 = atomicAdd(&g_degi[c0], 1);
    int rank1 = atomicAdd(&g_degi[c1], 1);
    int e = 2 * e2;
    g_rc[e]     = make_int2(r0, c0 | (rank0 << 17));
    g_rc[e + 1] = make_int2(r1, c1 | (rank1 << 17));
}

// Single-pass scan + finalize: 98 resident blocks, local shuffle scan,
// grid-arrive, cross-block prefix, then start/dinv/dx per node.
__global__ void k_scan(const float* __restrict__ x) {
    cudaGridDependencySynchronize();   // PDL: wait for convert
    __shared__ int ws[32];
    __shared__ int s_excl;
    int lane = threadIdx.x & 31;
    int warp = threadIdx.x >> 5;
    int i = blockIdx.x * 1024 + threadIdx.x;
    int deg = (i < N_NODES) ? g_degi[i] : 0;
    int s = deg;
#pragma unroll
    for (int o = 1; o < 32; o <<= 1) {
        int t = __shfl_up_sync(0xffffffffu, s, o);
        if (lane >= o) s += t;
    }
    if (lane == 31) ws[warp] = s;
    __syncthreads();
    if (warp == 0) {
        int w = ws[lane];
#pragma unroll
        for (int o = 1; o < 32; o <<= 1) {
            int t = __shfl_up_sync(0xffffffffu, w, o);
            if (lane >= o) w += t;
        }
        ws[lane] = w;
    }
    __syncthreads();
    int incl = s + (warp ? ws[warp - 1] : 0);

    if (threadIdx.x == 1023) {
        g_part[blockIdx.x] = incl;      // block total
        __threadfence();
        atomicAdd(&g_arrive, 1);
    }
    if (warp == 0) {
        if (lane == 0) {
            while (atomicAdd(&g_arrive, 0) < NB_SCAN) { }
        }
        __syncwarp();
        __threadfence();
        int acc = 0;
        for (int b = lane; b < blockIdx.x; b += 32)
            acc += g_part[b];
#pragma unroll
        for (int o = 16; o; o >>= 1)
            acc += __shfl_xor_sync(0xffffffffu, acc, o);
        if (lane == 0) s_excl = acc;
    }
    __syncthreads();

    if (i < N_NODES) {
        g_start[i] = incl - deg + s_excl;
        float dinv = rsqrtf((float)deg + 1.0f);
        g_dinv[i] = dinv;
        float2 xv = ((const float2*)x)[i];
        g_dx[i] = make_float2(dinv * xv.x, dinv * xv.y);
    }
}

// Atomic-free CSR fill: 2 edges/thread, packed ranks, streaming csr writes.
__global__ void k_fill() {
    cudaGridDependencySynchronize();   // PDL: wait for scan
    int e2 = blockIdx.x * blockDim.x + threadIdx.x;
    if (e2 >= E_EDGES / 2) return;
    int4 rr = ((const int4*)g_rc)[e2];   // (r0, y0, r1, y1)
    int c0 = rr.y & COL_MASK, k0 = rr.y >> 17;
    int c1 = rr.w & COL_MASK, k1 = rr.w >> 17;
    int s0 = __ldg(&g_start[c0]);
    int s1 = __ldg(&g_start[c1]);
    __stcs(&g_csr[s0 + k0], rr.x);
    __stcs(&g_csr[s1 + k1], rr.z);
}

// ---------------- layer 1: gather then tiled GEMM -----------------------------

// Thread-per-node: p[v] = dinv * (sum_{r in in(v)} dx[r] + dx[v])
__global__ void k_gather1() {
    cudaGridDependencySynchronize();   // PDL: wait for fill
    int v = blockIdx.x * blockDim.x + threadIdx.x;
    if (v >= N_NODES) return;
    int start = g_start[v];
    int deg   = g_degi[v];
    float a0 = 0.0f, a1 = 0.0f;
    int i = 0;
    for (; i + 4 <= deg; i += 4) {
        int r0 = g_csr[start + i];
        int r1 = g_csr[start + i + 1];
        int r2 = g_csr[start + i + 2];
        int r3 = g_csr[start + i + 3];
        float2 d0 = g_dx[r0], d1 = g_dx[r1], d2 = g_dx[r2], d3 = g_dx[r3];
        a0 += d0.x + d1.x + d2.x + d3.x;
        a1 += d0.y + d1.y + d2.y + d3.y;
    }
    for (; i < deg; i++) {
        float2 d = g_dx[g_csr[start + i]];
        a0 += d.x;
        a1 += d.y;
    }
    float dinv = g_dinv[v];
    float2 dxv = g_dx[v];
    g_p[v] = make_float2(dinv * (a0 + dxv.x), dinv * (a1 + dxv.y));
}

// Tiled GEMM: for 128-node tile, H[64][128] = relu(p @ W1 + b1) in shared,
// then s2 = dinv * (H^T @ W2) with 4n x 4k register tiles.
// PDL: weights staged BEFORE the dependency sync (they're harness inputs).
__global__ void k_mlp1(const float* __restrict__ W1,
                       const float* __restrict__ b1,
                       const float* __restrict__ W2) {
    __shared__ float sW1a[64], sW1b[64], sb1[64];
    __shared__ float sW2s[64][32];
    __shared__ float sH[64][128];
    __shared__ float sp0[128], sp1[128], sdinv[128];

    int tid = threadIdx.x;
    int base = blockIdx.x * 128;

    for (int i = tid; i < 64; i += 256) {
        sW1a[i] = W1[i];
        sW1b[i] = W1[64 + i];
        sb1[i]  = b1[i];
    }
    for (int i = tid; i < 2048; i += 256)
        sW2s[i >> 5][i & 31] = W2[i];

    cudaGridDependencySynchronize();   // PDL: now wait for gather1's g_p

    if (tid < 128) {
        int gn = base + tid;
        if (gn < N_NODES) {
            float2 p = g_p[gn];
            sp0[tid] = p.x;
            sp1[tid] = p.y;
            sdinv[tid] = g_dinv[gn];
        } else {
            sp0[tid] = 0.0f; sp1[tid] = 0.0f; sdinv[tid] = 0.0f;
        }
    }
    __syncthreads();

    for (int idx = tid; idx < 8192; idx += 256) {
        int j = idx >> 7, n = idx & 127;
        float h = fmaf(sp0[n], sW1a[j], fmaf(sp1[n], sW1b[j], sb1[j]));
        sH[j][n] = fmaxf(h, 0.0f);
    }
    __syncthreads();

    int kt = tid & 7, nt = tid >> 3;
    int n0 = nt * 4, k0 = kt * 4;
    float4 acc0 = make_float4(0,0,0,0), acc1 = acc0, acc2 = acc0, acc3 = acc0;
#pragma unroll
    for (int j = 0; j < 64; j++) {
        float4 h4 = *(const float4*)&sH[j][n0];
        float4 w4 = *(const float4*)&sW2s[j][k0];
        acc0.x = fmaf(h4.x, w4.x, acc0.x); acc0.y = fmaf(h4.x, w4.y, acc0.y);
        acc0.z = fmaf(h4.x, w4.z, acc0.z); acc0.w = fmaf(h4.x, w4.w, acc0.w);
        acc1.x = fmaf(h4.y, w4.x, acc1.x); acc1.y = fmaf(h4.y, w4.y, acc1.y);
        acc1.z = fmaf(h4.y, w4.z, acc1.z); acc1.w = fmaf(h4.y, w4.w, acc1.w);
        acc2.x = fmaf(h4.z, w4.x, acc2.x); acc2.y = fmaf(h4.z, w4.y, acc2.y);
        acc2.z = fmaf(h4.z, w4.z, acc2.z); acc2.w = fmaf(h4.z, w4.w, acc2.w);
        acc3.x = fmaf(h4.w, w4.x, acc3.x); acc3.y = fmaf(h4.w, w4.y, acc3.y);
        acc3.z = fmaf(h4.w, w4.z, acc3.z); acc3.w = fmaf(h4.w, w4.w, acc3.w);
    }
    float4 accs[4] = {acc0, acc1, acc2, acc3};
#pragma unroll
    for (int a = 0; a < 4; a++) {
        int n = n0 + a, gn = base + n;
        if (gn < N_NODES) {
            float d = sdinv[n];
            __half2 h01 = __floats2half2_rn(d * accs[a].x, d * accs[a].y);
            __half2 h23 = __floats2half2_rn(d * accs[a].z, d * accs[a].w);
            uint2 o;
            o.x = *(unsigned*)&h01;
            o.y = *(unsigned*)&h23;
            *(uint2*)&g_s2[gn * 32 + k0] = o;
        }
    }
}

// ---------------- layer 2: gather then tiled GEMM -----------------------------

// Warp-per-node, 16 rows in flight (pairwise fp16 hadd2 tree before cvt).
// Writes pre2 = dinv*(agg + s2[v]) fp16. 512-thread blocks.
__global__ void k_gather2() {
    cudaGridDependencySynchronize();   // PDL: wait for mlp1's g_s2
    int warp = threadIdx.x >> 5;
    int lane = threadIdx.x & 31;
    int v = blockIdx.x * 16 + warp;
    if (v >= N_NODES) return;

    int sub = lane >> 2;        // 0..7 row-groups
    int q   = lane & 3;         // dims 8q..8q+7
    int start = g_start[v];
    int deg   = g_degi[v];

    const uint4* s2v = (const uint4*)g_s2;
    float S[8] = {0.f,0.f,0.f,0.f,0.f,0.f,0.f,0.f};
    int i = sub;
    for (; i + 8 < deg; i += 16) {
        int r1 = g_csr[start + i];
        int r2 = g_csr[start + i + 8];
        uint4 u = s2v[r1 * 4 + q];
        uint4 w = s2v[r2 * 4 + q];
        __half2 h0 = __hadd2(*(const __half2*)&u.x, *(const __half2*)&w.x);
        __half2 h1 = __hadd2(*(const __half2*)&u.y, *(const __half2*)&w.y);
        __half2 h2 = __hadd2(*(const __half2*)&u.z, *(const __half2*)&w.z);
        __half2 h3 = __hadd2(*(const __half2*)&u.w, *(const __half2*)&w.w);
        float2 f0 = __half22float2(h0);
        float2 f1 = __half22float2(h1);
        float2 f2 = __half22float2(h2);
        float2 f3 = __half22float2(h3);
        S[0] += f0.x; S[1] += f0.y; S[2] += f1.x; S[3] += f1.y;
        S[4] += f2.x; S[5] += f2.y; S[6] += f3.x; S[7] += f3.y;
    }
    if (i < deg) {
        int r = g_csr[start + i];
        uint4 u = s2v[r * 4 + q];
        float2 f0 = __half22float2(*(const __half2*)&u.x);
        float2 f1 = __half22float2(*(const __half2*)&u.y);
        float2 f2 = __half22float2(*(const __half2*)&u.z);
        float2 f3 = __half22float2(*(const __half2*)&u.w);
        S[0] += f0.x; S[1] += f0.y; S[2] += f1.x; S[3] += f1.y;
        S[4] += f2.x; S[5] += f2.y; S[6] += f3.x; S[7] += f3.y;
    }
#pragma unroll
    for (int o = 4; o <= 16; o <<= 1) {
#pragma unroll
        for (int t = 0; t < 8; t++)
            S[t] += __shfl_xor_sync(0xffffffffu, S[t], o);
    }

    if (sub == 0) {
        float dinv = g_dinv[v];
        uint4 u = s2v[v * 4 + q];
        float2 f0 = __half22float2(*(const __half2*)&u.x);
        float2 f1 = __half22float2(*(const __half2*)&u.y);
        float2 f2 = __half22float2(*(const __half2*)&u.z);
        float2 f3 = __half22float2(*(const __half2*)&u.w);
        __half2 p0 = __floats2half2_rn(dinv * (S[0] + f0.x), dinv * (S[1] + f0.y));
        __half2 p1 = __floats2half2_rn(dinv * (S[2] + f1.x), dinv * (S[3] + f1.y));
        __half2 p2 = __floats2half2_rn(dinv * (S[4] + f2.x), dinv * (S[5] + f2.y));
        __half2 p3 = __floats2half2_rn(dinv * (S[6] + f3.x), dinv * (S[7] + f3.y));
        uint4 o;
        o.x = *(unsigned*)&p0; o.y = *(unsigned*)&p1;
        o.z = *(unsigned*)&p2; o.w = *(unsigned*)&p3;
        ((uint4*)g_pre2)[v * 4 + q] = o;
    }
}

// Tiled GEMM: h2 = relu(pre2 + b2) staged to shared, then
// (a|c)[n][k] = sum_j h2[n][j] * Wq[j][k].
__global__ void k_mlp2(const float* __restrict__ b2,
                       const float* __restrict__ Wm1) {
    __shared__ float sW[32][32];
    __shared__ float sH2[32][132];
    __shared__ float sb2[32];

    int tid = threadIdx.x;
    int base = blockIdx.x * 128;

    if (tid < 32) sb2[tid] = b2[tid];
    for (int i = tid; i < 1024; i += 256) {
        int j = i >> 5, k = i & 31;
        sW[j][k] = Wm1[((k < 16 ? j : 32 + j) << 4) + (k & 15)];
    }

    cudaGridDependencySynchronize();   // PDL: now wait for gather2's g_pre2
    __syncthreads();

    const __half2* src = (const __half2*)g_pre2;
    for (int idx = tid; idx < 2048; idx += 256) {
        int n = idx >> 4;
        int j2 = idx & 15;
        int gn = base + n;
        float2 f = make_float2(0.0f, 0.0f);
        if (gn < N_NODES)
            f = __half22float2(src[gn * 16 + j2]);
        int j = 2 * j2;
        sH2[j][n]     = fmaxf(f.x + sb2[j],     0.0f);
        sH2[j + 1][n] = fmaxf(f.y + sb2[j + 1], 0.0f);
    }
    __syncthreads();

    int kt = tid & 7, nt = tid >> 3;
    int n0 = nt * 4, k0 = kt * 4;
    float4 acc0 = make_float4(0,0,0,0), acc1 = acc0, acc2 = acc0, acc3 = acc0;
#pragma unroll
    for (int j = 0; j < 32; j++) {
        float4 h4 = *(const float4*)&sH2[j][n0];
        float4 w4 = *(const float4*)&sW[j][k0];
        acc0.x = fmaf(h4.x, w4.x, acc0.x); acc0.y = fmaf(h4.x, w4.y, acc0.y);
        acc0.z = fmaf(h4.x, w4.z, acc0.z); acc0.w = fmaf(h4.x, w4.w, acc0.w);
        acc1.x = fmaf(h4.y, w4.x, acc1.x); acc1.y = fmaf(h4.y, w4.y, acc1.y);
        acc1.z = fmaf(h4.y, w4.z, acc1.z); acc1.w = fmaf(h4.y, w4.w, acc1.w);
        acc2.x = fmaf(h4.z, w4.x, acc2.x); acc2.y = fmaf(h4.z, w4.y, acc2.y);
        acc2.z = fmaf(h4.z, w4.z, acc2.z); acc2.w = fmaf(h4.z, w4.w, acc2.w);
        acc3.x = fmaf(h4.w, w4.x, acc3.x); acc3.y = fmaf(h4.w, w4.y, acc3.y);
        acc3.z = fmaf(h4.w, w4.z, acc3.z); acc3.w = fmaf(h4.w, w4.w, acc3.w);
    }
    float4 accs[4] = {acc0, acc1, acc2, acc3};
#pragma unroll
    for (int a = 0; a < 4; a++) {
        int n = n0 + a, gn = base + n;
        if (gn < N_NODES) {
            __half2 h01 = __floats2half2_rn(accs[a].x, accs[a].y);
            __half2 h23 = __floats2half2_rn(accs[a].z, accs[a].w);
            uint2 o;
            o.x = *(unsigned*)&h01;
            o.y = *(unsigned*)&h23;
            if (k0 < 16) *(uint2*)&g_a[gn * 16 + k0]        = o;
            else         *(uint2*)&g_c[gn * 16 + (k0 - 16)] = o;
        }
    }
}

// ---------------- edge MLP -----------------------------------------------------

// 2 lanes per edge (8 dims each, uint4 gathers); weights staged in shared float4.
__global__ void k_edge(const float* __restrict__ ea,
                       const float* __restrict__ Wm1,
                       const float* __restrict__ bm1,
                       const float* __restrict__ Wm2,
                       const float* __restrict__ bm2,
                       float* __restrict__ out) {
    __shared__ float4 swq[16];   // (W64, W65, bm1, Wm2) per dim
    __shared__ float sbm2;
    if (threadIdx.x < 16)
        swq[threadIdx.x] = make_float4(Wm1[64 * 16 + threadIdx.x],
                                       Wm1[65 * 16 + threadIdx.x],
                                       bm1[threadIdx.x],
                                       Wm2[threadIdx.x]);
    if (threadIdx.x == 0) sbm2 = bm2[0];

    cudaGridDependencySynchronize();   // PDL: now wait for mlp2's g_a/g_c
    __syncthreads();

    int t = blockIdx.x * blockDim.x + threadIdx.x;
    int e = t >> 1;
    int g = t & 1;              // dims 8g..8g+7
    if (e >= E_EDGES) return;

    int2 rc = g_rc[e];
    int rnode = rc.x;
    int cnode = rc.y & COL_MASK;
    float2 eav = ((const float2*)ea)[e];
    uint4 au = ((const uint4*)g_a)[rnode * 2 + g];
    uint4 cu = ((const uint4*)g_c)[cnode * 2 + g];

    float af[8], cf[8];
    {
        float2 f;
        f = __half22float2(*(const __half2*)&au.x); af[0]=f.x; af[1]=f.y;
        f = __half22float2(*(const __half2*)&au.y); af[2]=f.x; af[3]=f.y;
        f = __half22float2(*(const __half2*)&au.z); af[4]=f.x; af[5]=f.y;
        f = __half22float2(*(const __half2*)&au.w); af[6]=f.x; af[7]=f.y;
        f = __half22float2(*(const __half2*)&cu.x); cf[0]=f.x; cf[1]=f.y;
        f = __half22float2(*(const __half2*)&cu.y); cf[2]=f.x; cf[3]=f.y;
        f = __half22float2(*(const __half2*)&cu.z); cf[4]=f.x; cf[5]=f.y;
        f = __half22float2(*(const __half2*)&cu.w); cf[6]=f.x; cf[7]=f.y;
    }

    float p = 0.0f;
#pragma unroll
    for (int j = 0; j < 8; j++) {
        float4 w = swq[8 * g + j];
        float hm = fmaxf(fmaf(eav.x, w.x, fmaf(eav.y, w.y, af[j] + cf[j] + w.z)), 0.0f);
        p = fmaf(hm, w.w, p);
    }
    p += __shfl_xor_sync(0xffffffffu, p, 1, 2);
    if (g == 0) out[e] = p + sbm2;
}

// ---------------- launch ------------------------------------------------------

template <typename K, typename... Args>
static void launch_pdl(K kernel, unsigned grid, unsigned block, Args... args) {
    cudaLaunchConfig_t cfg = {};
    cfg.gridDim = {grid, 1, 1};
    cfg.blockDim = {block, 1, 1};
    cfg.dynamicSmemBytes = 0;
    cfg.stream = 0;
    cudaLaunchAttribute attr[1];
    attr[0].id = cudaLaunchAttributeProgrammaticStreamSerialization;
    attr[0].val.programmaticStreamSerializationAllowed = 1;
    cfg.attrs = attr;
    cfg.numAttrs = 1;
    cudaLaunchKernelEx(&cfg, kernel, args...);
}

extern "C" void kernel_launch(void* const* d_in, const int* in_sizes, int n_in,
                              void* d_out, int out_size) {
    const float* x   = (const float*)d_in[0];
    const void*  ei  = d_in[1];
    const float* ea  = (const float*)d_in[2];
    const float* W1  = (const float*)d_in[3];
    const float* b1  = (const float*)d_in[4];
    const float* W2  = (const float*)d_in[5];
    const float* b2  = (const float*)d_in[6];
    const float* Wm1 = (const float*)d_in[7];
    const float* bm1 = (const float*)d_in[8];
    const float* Wm2 = (const float*)d_in[9];
    const float* bm2 = (const float*)d_in[10];
    float* out = (float*)d_out;

    long long ethreads = (long long)E_EDGES * 2;
    unsigned eblocks = (unsigned)((ethreads + 511) / 512);
    unsigned ntiles = (N_NODES + 127) / 128;

    k_zero_detect<<<(N_NODES + 255) / 256 + 1, 256>>>((const int*)ei);
    launch_pdl(k_convert, (E_EDGES / 2 + 255) / 256, 256, ei);
    launch_pdl(k_scan, NB_SCAN, 1024, x);
    launch_pdl(k_fill, (E_EDGES / 2 + 255) / 256, 256);
    launch_pdl(k_gather1, (N_NODES + 255) / 256, 256);
    launch_pdl(k_mlp1, ntiles, 256, W1, b1, W2);
    launch_pdl(k_gather2, (N_NODES + 15) / 16, 512);
    launch_pdl(k_mlp2, ntiles, 256, b2, Wm1);
    launch_pdl(k_edge, eblocks, 512, ea, Wm1, bm1, Wm2, bm2, out);
}